// round 14
// baseline (speedup 1.0000x reference)
#include <cuda_runtime.h>
#include <cstdint>
#include <cstddef>

#define NB        16
#define NPTS      131072
#define NSAMP     4096
#define NTHREADS  1024
#define NWARPS    (NTHREADS / 32)

// Plain scalar device-global scratch.
__device__ float g_dmin[(size_t)NB * NPTS];

__global__ void __launch_bounds__(NTHREADS, 1)
fps_plain(const float* __restrict__ xyz, float* __restrict__ out)
{
    __shared__ unsigned long long warpRed[NWARPS];
    __shared__ float bc[3];

    const int b    = blockIdx.x;
    const int tid  = threadIdx.x;
    const int lane = tid & 31;
    const int wid  = tid >> 5;

    const float* pb = xyz + (size_t)b * NPTS * 3;   // this batch, AoS
    float*       dm = g_dmin + (size_t)b * NPTS;

    // Init dmin = +inf every launch (replay-safe).
    const float INF = __int_as_float(0x7f800000);
    for (int p = tid; p < NPTS; p += NTHREADS) dm[p] = INF;
    __syncthreads();

    float cx = pb[0], cy = pb[1], cz = pb[2];       // first centroid = point 0
    if (tid == 0) out[b * NSAMP] = 0.0f;            // output dtype = float32

    for (int k = 0; k < NSAMP - 1; ++k) {
        float bestVal = -1.0f;
        int   bestIdx = 0;

        for (int p = tid; p < NPTS; p += NTHREADS) {
            float dx = __fsub_rn(pb[3 * p + 0], cx);
            float dy = __fsub_rn(pb[3 * p + 1], cy);
            float dz = __fsub_rn(pb[3 * p + 2], cz);
            // FLAVOR B: contracted evaluation of ((dx^2 + dy^2) + dz^2):
            // d = fma(dz,dz, fma(dy,dy, dx*dx))
            float d  = __fmaf_rn(dz, dz, __fmaf_rn(dy, dy, __fmul_rn(dx, dx)));
            float dmn = fminf(dm[p], d);
            dm[p] = dmn;
            if (dmn > bestVal) { bestVal = dmn; bestIdx = p; }  // strict >: first index wins
        }

        // Packed key (value desc, index asc); monotone for non-negative values.
        unsigned long long key =
            ((unsigned long long)__float_as_uint(bestVal) << 32) |
            (unsigned long long)(0xFFFFFFFFu - (unsigned)bestIdx);

#pragma unroll
        for (int o = 16; o; o >>= 1) {
            unsigned long long other = __shfl_xor_sync(0xFFFFFFFFu, key, o);
            if (other > key) key = other;
        }
        if (lane == 0) warpRed[wid] = key;
        __syncthreads();

        if (wid == 0) {
            unsigned long long bk = warpRed[lane];   // exactly 32 warps
#pragma unroll
            for (int o = 16; o; o >>= 1) {
                unsigned long long other = __shfl_xor_sync(0xFFFFFFFFu, bk, o);
                if (other > bk) bk = other;
            }
            if (lane == 0) {
                unsigned widx = 0xFFFFFFFFu - (unsigned)(bk & 0xFFFFFFFFull);
                bc[0] = pb[3 * (size_t)widx + 0];
                bc[1] = pb[3 * (size_t)widx + 1];
                bc[2] = pb[3 * (size_t)widx + 2];
                out[b * NSAMP + k + 1] = (float)widx;   // float output
            }
        }
        __syncthreads();
        cx = bc[0]; cy = bc[1]; cz = bc[2];
        __syncthreads();   // protect bc from next iteration's lane0 write
    }
}

extern "C" void kernel_launch(void* const* d_in, const int* in_sizes, int n_in,
                              void* d_out, int out_size)
{
    (void)in_sizes; (void)n_in; (void)out_size;
    const float* xyz = (const float*)d_in[0];
    float* out = (float*)d_out;   // __output__ dtype = float32

    fps_plain<<<NB, NTHREADS>>>(xyz, out);
}

// round 15
// speedup vs baseline: 3.9978x; 3.9978x over previous
#include <cuda_runtime.h>
#include <cstdint>
#include <cstddef>

#define NB        16
#define NPTS      131072
#define NSAMP     4096
#define NCTA_B    8                        // CTAs per batch
#define PTS_CTA   (NPTS / NCTA_B)          // 16384
#define NTHREADS  512
#define NWARPS    (NTHREADS / 32)          // 16
#define PTS_THR   (PTS_CTA / NTHREADS)     // 32

// Global mailboxes (double-buffered by parity). Tags are k+1; stale values
// from a previous graph replay never alias the polled tag at the same parity
// early in a new launch (4095/4094 vs 1/2), so no reset needed.
__device__ unsigned long long g_key[2][NB][NCTA_B];
__device__ float              g_wx [2][NB][NCTA_B];
__device__ float              g_wy [2][NB][NCTA_B];
__device__ float              g_wz [2][NB][NCTA_B];
__device__ volatile unsigned  g_tag[2][NB][NCTA_B];

#define COORD_BYTES (3 * PTS_CTA * 4)                  // 196608
#define WARPRED_OFF COORD_BYTES
#define BCAST_OFF   (WARPRED_OFF + NWARPS * 8)
#define SMEM_TOTAL  (BCAST_OFF + 16)                   // 196752

__global__ void __launch_bounds__(NTHREADS, 1)
fps_smem(const float* __restrict__ xyz, float* __restrict__ out)
{
    extern __shared__ char smem[];
    float* sx = (float*)smem;
    float* sy = sx + PTS_CTA;
    float* sz = sy + PTS_CTA;
    unsigned long long* warpRed = (unsigned long long*)(smem + WARPRED_OFF);
    float* bcast = (float*)(smem + BCAST_OFF);   // winner x,y,z

    const int tid  = threadIdx.x;
    const int rank = blockIdx.x & (NCTA_B - 1);
    const int b    = blockIdx.x >> 3;
    const int wid  = tid >> 5;
    const int lane = tid & 31;

    // Stage this CTA's 16384 points into SMEM (SoA).
    const float* bbase = xyz + (size_t)b * NPTS * 3 + (size_t)rank * PTS_CTA * 3;
    for (int j = tid; j < PTS_CTA; j += NTHREADS) {
        sx[j] = bbase[3 * j + 0];
        sy[j] = bbase[3 * j + 1];
        sz[j] = bbase[3 * j + 2];
    }

    // Per-point running min-distance in registers.
    float dmin[PTS_THR];
#pragma unroll
    for (int i = 0; i < PTS_THR; i++) dmin[i] = __int_as_float(0x7f800000);

    // First centroid = point 0 of the batch.
    const float* b0 = xyz + (size_t)b * NPTS * 3;
    float cx = __ldg(b0 + 0), cy = __ldg(b0 + 1), cz = __ldg(b0 + 2);

    if (rank == 0 && tid == 0) out[b * NSAMP] = 0.0f;   // float output
    __syncthreads();

    for (int k = 0; k < NSAMP - 1; ++k) {
        // ---- scan 32 points/thread from SMEM; verified FMA arithmetic ----
        float bestVal = -1.0f;
        int   bestIdx = 0;
#pragma unroll
        for (int i = 0; i < PTS_THR; i++) {
            int p = i * NTHREADS + tid;
            float dx = __fsub_rn(sx[p], cx);
            float dy = __fsub_rn(sy[p], cy);
            float dz = __fsub_rn(sz[p], cz);
            float d  = __fmaf_rn(dz, dz, __fmaf_rn(dy, dy, __fmul_rn(dx, dx)));
            float dm = fminf(dmin[i], d);
            dmin[i]  = dm;
            if (dm > bestVal) { bestVal = dm; bestIdx = p; }  // strict >: lowest p wins
        }

        unsigned gidx = (unsigned)(rank * PTS_CTA + bestIdx);
        unsigned long long key =
            ((unsigned long long)__float_as_uint(bestVal) << 32) |
            (unsigned long long)(0xFFFFFFFFu - gidx);

        // ---- warp reduce ----
#pragma unroll
        for (int o = 16; o; o >>= 1) {
            unsigned long long other = __shfl_xor_sync(0xFFFFFFFFu, key, o);
            if (other > key) key = other;
        }
        if (lane == 0) warpRed[wid] = key;
        __syncthreads();

        const int par = k & 1;

        if (wid == 0) {
            // ---- block reduce over 16 warp winners ----
            unsigned long long bk = (lane < NWARPS) ? warpRed[lane] : 0ull;
#pragma unroll
            for (int o = 16; o; o >>= 1) {
                unsigned long long other = __shfl_xor_sync(0xFFFFFFFFu, bk, o);
                if (other > bk) bk = other;
            }

            // ---- publish candidate (key + winner coords) ----
            if (lane == 0) {
                unsigned widx  = 0xFFFFFFFFu - (unsigned)(bk & 0xFFFFFFFFull);
                int      local = (int)(widx & (PTS_CTA - 1));
                g_key[par][b][rank] = bk;
                g_wx [par][b][rank] = sx[local];
                g_wy [par][b][rank] = sy[local];
                g_wz [par][b][rank] = sz[local];
                __threadfence();
                g_tag[par][b][rank] = (unsigned)(k + 1);
            }

            // ---- consume all 8 candidates (lanes 0..7 poll in parallel) ----
            unsigned long long ck = 0ull;
            float cwx = 0.f, cwy = 0.f, cwz = 0.f;
            if (lane < NCTA_B) {
                while (g_tag[par][b][lane] != (unsigned)(k + 1)) { }
                __threadfence();
                ck  = *(volatile unsigned long long*)&g_key[par][b][lane];
                cwx = *(volatile float*)&g_wx[par][b][lane];
                cwy = *(volatile float*)&g_wy[par][b][lane];
                cwz = *(volatile float*)&g_wz[par][b][lane];
            }
#pragma unroll
            for (int o = 4; o; o >>= 1) {
                unsigned long long ok = __shfl_xor_sync(0xFFFFFFFFu, ck,  o);
                float ox = __shfl_xor_sync(0xFFFFFFFFu, cwx, o);
                float oy = __shfl_xor_sync(0xFFFFFFFFu, cwy, o);
                float oz = __shfl_xor_sync(0xFFFFFFFFu, cwz, o);
                if (ok > ck) { ck = ok; cwx = ox; cwy = oy; cwz = oz; }
            }
            if (lane == 0) {
                bcast[0] = cwx; bcast[1] = cwy; bcast[2] = cwz;
                if (rank == 0)
                    out[b * NSAMP + k + 1] =
                        (float)(0xFFFFFFFFu - (unsigned)(ck & 0xFFFFFFFFull));
            }
        }
        __syncthreads();
        cx = bcast[0]; cy = bcast[1]; cz = bcast[2];
        __syncthreads();   // protect bcast/warpRed from next iteration's writes
    }
}

extern "C" void kernel_launch(void* const* d_in, const int* in_sizes, int n_in,
                              void* d_out, int out_size)
{
    (void)in_sizes; (void)n_in; (void)out_size;
    const float* xyz = (const float*)d_in[0];
    float* out = (float*)d_out;

    cudaFuncSetAttribute(fps_smem, cudaFuncAttributeMaxDynamicSharedMemorySize,
                         SMEM_TOTAL);

    dim3 grid(NB * NCTA_B);   // 128 CTAs, 1 per SM, single wave (148 SMs)
    dim3 block(NTHREADS);
    fps_smem<<<grid, block, SMEM_TOTAL>>>(xyz, out);
}

// round 16
// speedup vs baseline: 4.9052x; 1.2270x over previous
#include <cuda_runtime.h>
#include <cstdint>
#include <cstddef>

#define NB        16
#define NPTS      131072
#define NSAMP     4096
#define CLUSTER_X 8
#define PTS_CTA   (NPTS / CLUSTER_X)      // 16384
#define NTHREADS  512
#define NWARPS    (NTHREADS / 32)         // 16
#define PTS_THR   (PTS_CTA / NTHREADS)    // 32

#define COORD_BYTES (3 * PTS_CTA * 4)     // 196608
#define WARPRED_OFF COORD_BYTES           // 16 * 8B
#define CRED_OFF    (WARPRED_OFF + NWARPS * 8)
#define SLOT_BYTES  32                    // key(8) + x,y,z(12) + pad
#define SMEM_TOTAL  (CRED_OFF + 2 * CLUSTER_X * SLOT_BYTES)  // 197248

__device__ __forceinline__ unsigned smem_u32(const void* p) {
    return (unsigned)__cvta_generic_to_shared(p);
}

__global__ void __launch_bounds__(NTHREADS, 1) __cluster_dims__(CLUSTER_X, 1, 1)
fps_cluster(const float* __restrict__ xyz, float* __restrict__ out)
{
    extern __shared__ char smem[];
    float* sx = (float*)smem;
    float* sy = sx + PTS_CTA;
    float* sz = sy + PTS_CTA;
    unsigned long long* warpRed = (unsigned long long*)(smem + WARPRED_OFF);
    char* cred = smem + CRED_OFF;

    const int tid  = threadIdx.x;
    const int rank = blockIdx.x & (CLUSTER_X - 1);
    const int b    = blockIdx.x >> 3;
    const int wid  = tid >> 5;
    const int lane = tid & 31;

    // Stage this CTA's 16384 points into SMEM (SoA).
    const float* bbase = xyz + (size_t)b * NPTS * 3 + (size_t)rank * PTS_CTA * 3;
    for (int j = tid; j < PTS_CTA; j += NTHREADS) {
        sx[j] = bbase[3 * j + 0];
        sy[j] = bbase[3 * j + 1];
        sz[j] = bbase[3 * j + 2];
    }

    // Per-point running min-distance in registers.
    float dmin[PTS_THR];
#pragma unroll
    for (int i = 0; i < PTS_THR; i++) dmin[i] = __int_as_float(0x7f800000);

    // First centroid = point 0 of the batch.
    const float* b0 = xyz + (size_t)b * NPTS * 3;
    float cx = __ldg(b0 + 0), cy = __ldg(b0 + 1), cz = __ldg(b0 + 2);

    if (rank == 0 && tid == 0) out[b * NSAMP] = 0.0f;   // float output
    __syncthreads();

    for (int k = 0; k < NSAMP - 1; ++k) {
        // ---- scan 32 points/thread from SMEM (verified FMA arithmetic) ----
        float bestVal = -1.0f;
        int   bestIdx = 0;
#pragma unroll
        for (int i = 0; i < PTS_THR; i++) {
            int p = i * NTHREADS + tid;
            float dx = __fsub_rn(sx[p], cx);
            float dy = __fsub_rn(sy[p], cy);
            float dz = __fsub_rn(sz[p], cz);
            float d  = __fmaf_rn(dz, dz, __fmaf_rn(dy, dy, __fmul_rn(dx, dx)));
            float dm = fminf(dmin[i], d);
            dmin[i]  = dm;
            if (dm > bestVal) { bestVal = dm; bestIdx = p; }  // strict >: lowest p wins
        }

        unsigned gidx = (unsigned)(rank * PTS_CTA + bestIdx);
        unsigned long long key =
            ((unsigned long long)__float_as_uint(bestVal) << 32) |
            (unsigned long long)(0xFFFFFFFFu - gidx);

        // ---- warp reduce ----
#pragma unroll
        for (int o = 16; o; o >>= 1) {
            unsigned long long other = __shfl_xor_sync(0xFFFFFFFFu, key, o);
            if (other > key) key = other;
        }
        if (lane == 0) warpRed[wid] = key;
        __syncthreads();

        const int par = k & 1;

        // ---- block reduce + publish candidate to all 8 CTAs (DSMEM) ----
        if (wid == 0) {
            unsigned long long bk = (lane < NWARPS) ? warpRed[lane] : 0ull;
#pragma unroll
            for (int o = 16; o; o >>= 1) {
                unsigned long long other = __shfl_xor_sync(0xFFFFFFFFu, bk, o);
                if (other > bk) bk = other;
            }
            // Every lane of warp 0 now holds the block winner key.
            unsigned widx  = 0xFFFFFFFFu - (unsigned)(bk & 0xFFFFFFFFull);
            int      local = (int)(widx & (PTS_CTA - 1));
            float wx = sx[local], wy = sy[local], wz = sz[local];

            if (lane < CLUSTER_X) {
                unsigned slot = smem_u32(cred) +
                                (unsigned)(par * CLUSTER_X * SLOT_BYTES + rank * SLOT_BYTES);
                unsigned raddr;
                asm volatile("mapa.shared::cluster.u32 %0, %1, %2;"
                             : "=r"(raddr) : "r"(slot), "r"(lane));
                asm volatile("st.shared::cluster.u64 [%0], %1;"
                             :: "r"(raddr), "l"(bk) : "memory");
                asm volatile("st.shared::cluster.v2.f32 [%0], {%1, %2};"
                             :: "r"(raddr + 8), "f"(wx), "f"(wy) : "memory");
                asm volatile("st.shared::cluster.f32 [%0], %1;"
                             :: "r"(raddr + 16), "f"(wz) : "memory");
            }
        }

        // One cluster barrier per iteration (release on arrive / acquire on wait;
        // double-buffered slots make the single barrier sufficient).
        asm volatile("barrier.cluster.arrive.aligned;" ::: "memory");
        asm volatile("barrier.cluster.wait.aligned;"   ::: "memory");

        // ---- every thread reduces the 8 candidates locally (broadcast LDS) ----
        const char* cp = cred + par * CLUSTER_X * SLOT_BYTES;
        unsigned long long bk = 0ull;
        float wx = 0.f, wy = 0.f, wz = 0.f;
#pragma unroll
        for (int r = 0; r < CLUSTER_X; r++) {
            unsigned long long kk = *(const unsigned long long*)(cp + r * SLOT_BYTES);
            float xx = *(const float*)(cp + r * SLOT_BYTES + 8);
            float yy = *(const float*)(cp + r * SLOT_BYTES + 12);
            float zz = *(const float*)(cp + r * SLOT_BYTES + 16);
            if (kk > bk) { bk = kk; wx = xx; wy = yy; wz = zz; }
        }
        cx = wx; cy = wy; cz = wz;

        if (rank == 0 && tid == 0)
            out[b * NSAMP + k + 1] =
                (float)(0xFFFFFFFFu - (unsigned)(bk & 0xFFFFFFFFull));
    }
}

extern "C" void kernel_launch(void* const* d_in, const int* in_sizes, int n_in,
                              void* d_out, int out_size)
{
    (void)in_sizes; (void)n_in; (void)out_size;
    const float* xyz = (const float*)d_in[0];
    float* out = (float*)d_out;

    cudaFuncSetAttribute(fps_cluster, cudaFuncAttributeMaxDynamicSharedMemorySize,
                         SMEM_TOTAL);

    dim3 grid(NB * CLUSTER_X);   // 128 CTAs = 16 clusters of 8
    dim3 block(NTHREADS);
    fps_cluster<<<grid, block, SMEM_TOTAL>>>(xyz, out);
}